// round 1
// baseline (speedup 1.0000x reference)
#include <cuda_runtime.h>
#include <math.h>

// ============================================================================
// Compile-time real Clebsch-Gordan tensor (exact replica of the reference's
// _real_cg, evaluated at C++ compile time so zero coefficients vanish).
// ============================================================================
#define DH __host__ __device__

namespace cgct {

DH constexpr double fact(int n) {
    double r = 1.0;
    for (int i = 2; i <= n; ++i) r *= (double)i;
    return r;
}

DH constexpr double csqrt(double x) {
    if (x <= 0.0) return 0.0;
    double g = x < 1.0 ? 1.0 : x;
    for (int i = 0; i < 200; ++i) g = 0.5 * (g + x / g);
    return g;
}

DH constexpr int iabs(int x) { return x < 0 ? -x : x; }
DH constexpr double m1p(int k) { return (k % 2 != 0) ? -1.0 : 1.0; }

DH constexpr double clebsch(int j1, int m1, int j2, int m2, int j3, int m3) {
    if (m1 + m2 != m3) return 0.0;
    if (j3 < iabs(j1 - j2) || j3 > j1 + j2) return 0.0;
    double pre = csqrt((2.0 * j3 + 1.0) * fact(j1 + j2 - j3) * fact(j1 - j2 + j3) *
                       fact(-j1 + j2 + j3) / fact(j1 + j2 + j3 + 1));
    pre = pre * csqrt(fact(j3 + m3) * fact(j3 - m3) * fact(j1 - m1) *
                      fact(j1 + m1) * fact(j2 - m2) * fact(j2 + m2));
    double s = 0.0;
    for (int k = 0; k <= j1 + j2 + j3; ++k) {
        int d0 = k, d1 = j1 + j2 - j3 - k, d2 = j1 - m1 - k;
        int d3 = j2 + m2 - k, d4 = j3 - j2 + m1 + k, d5 = j3 - j1 - m2 + k;
        if (d0 < 0 || d1 < 0 || d2 < 0 || d3 < 0 || d4 < 0 || d5 < 0) continue;
        s += m1p(k) / (fact(d0) * fact(d1) * fact(d2) * fact(d3) * fact(d4) * fact(d5));
    }
    return pre * s;
}

struct C2 { double re, im; };
DH constexpr C2 cmul(C2 a, C2 b) { return {a.re * b.re - a.im * b.im, a.re * b.im + a.im * b.re}; }
DH constexpr C2 cconj(C2 a) { return {a.re, -a.im}; }

// U matrix element: row i (= m+l), col k, for degree l (complex->real SH basis change)
DH constexpr C2 Uel(int l, int i, int k) {
    double s2 = 1.0 / csqrt(2.0);
    int m = i - l;
    if (m == 0) return (k == l) ? C2{1.0, 0.0} : C2{0.0, 0.0};
    if (m > 0) {
        if (k == l + m) return C2{m1p(m) * s2, 0.0};
        if (k == l - m) return C2{s2, 0.0};
        return C2{0.0, 0.0};
    }
    // m < 0
    if (k == l + m) return C2{0.0, s2};
    if (k == l - m) return C2{0.0, -m1p(m) * s2};
    return C2{0.0, 0.0};
}

DH constexpr int l_of(int I) { return I == 0 ? 0 : (I < 4 ? 1 : 2); }
DH constexpr int o_of(int l) { return l == 0 ? 0 : (l == 1 ? 1 : 4); }

// CGC[I][J][K] of the 9x9x9 real-CG tensor (real + imag parts summed, as in ref)
DH constexpr double CGC(int I, int J, int K) {
    int l1 = l_of(I), l2 = l_of(J), l3 = l_of(K);
    if (l3 < iabs(l1 - l2) || l3 > l1 + l2) return 0.0;
    int i = I - o_of(l1), j = J - o_of(l2), kk = K - o_of(l3);
    double re = 0.0, im = 0.0;
    for (int a = 0; a < 2 * l1 + 1; ++a) {
        for (int b = 0; b < 2 * l2 + 1; ++b) {
            int m1 = a - l1, m2 = b - l2, m3 = m1 + m2;
            if (m3 < -l3 || m3 > l3) continue;
            int c = m3 + l3;
            double v = clebsch(l1, m1, l2, m2, l3, m3);
            if (v == 0.0) continue;
            C2 t = cmul(cmul(Uel(l1, i, a), Uel(l2, j, b)), cconj(Uel(l3, kk, c)));
            re += t.re * v;
            im += t.im * v;
        }
    }
    return re + im;
}

} // namespace cgct

// ============================================================================
// static-for for compile-time unrolled loops with constexpr indices
// ============================================================================
template <int I> struct IC { static constexpr int v = I; };
template <int N, class F>
__device__ __forceinline__ void sfor(F&& f) {
    if constexpr (N > 0) {
        sfor<N - 1>(f);
        f(IC<N - 1>{});
    }
}

// ============================================================================
// Problem constants & scratch
// ============================================================================
constexpr int NE = 320000;
constexpr int NN = 10000;
constexpr int FT = 32;

__device__ float g_rad[NE * 8];
__device__ float g_Y[NE * 9];
__device__ float g_x[NN * 9 * FT];
__device__ float g_y[NN * 9 * FT];

// Path lists
template <int IT> struct PathsT;
template <> struct PathsT<0> {
    static constexpr int NP = 3;
    static constexpr int L[3][3] = {{0,0,0},{0,1,1},{0,2,2}};
};
template <> struct PathsT<1> {
    static constexpr int NP = 15;
    static constexpr int L[15][3] = {
        {0,0,0},{0,1,1},{0,2,2},
        {1,0,1},{1,1,0},{1,1,1},{1,1,2},{1,2,1},{1,2,2},
        {2,0,2},{2,1,1},{2,1,2},{2,2,0},{2,2,1},{2,2,2}};
};
template <> struct PathsT<2> {
    static constexpr int NP = 3;
    static constexpr int L[3][3] = {{0,0,0},{1,1,0},{2,2,0}};
};

// ============================================================================
// Kernels
// ============================================================================
__global__ void geom_kernel(const float* __restrict__ dr,
                            const int* __restrict__ nbr, int E) {
    int e = blockIdx.x * blockDim.x + threadIdx.x;
    if (e >= E) return;
    float dx = dr[e * 3 + 0], dy = dr[e * 3 + 1], dz = dr[e * 3 + 2];
    float r2 = dx * dx + dy * dy + dz * dz + 1e-12f;
    float r = sqrtf(r2);
    float inv = 1.0f / r;
    float ux = dx * inv, uy = dy * inv, uz = dz * inv;

    float t = r * (1.0f / 6.0f);
    t = fminf(fmaxf(t, 0.0f), 1.0f - 1e-6f);
    float cut = (r < 6.0f) ? expf(1.0f - 1.0f / (1.0f - t * t)) : 0.0f;

    int ii = nbr[e], jj = nbr[E + e];
    float cm = cut * ((ii != jj) ? 1.0f : 0.0f);

    const float pre = 0.5773502691896258f;  // sqrt(2/6)
    float arg = 0.5235987755982988f * r;    // pi*r/6
    float s = pre * inv * cm;
#pragma unroll
    for (int n = 0; n < 8; ++n)
        g_rad[e * 8 + n] = s * sinf((float)(n + 1) * arg);

    const float c0 = 0.28209479177387814f, c1 = 0.4886025119029199f;
    const float c2a = 1.0925484305920792f, c2b = 0.31539156525252005f,
                c2c = 0.5462742152960396f;
    float* Yp = &g_Y[e * 9];
    Yp[0] = c0;
    Yp[1] = c1 * uy;
    Yp[2] = c1 * uz;
    Yp[3] = c1 * ux;
    Yp[4] = c2a * ux * uy;
    Yp[5] = c2a * uy * uz;
    Yp[6] = c2b * (3.0f * uz * uz - 1.0f);
    Yp[7] = c2a * ux * uz;
    Yp[8] = c2c * (ux * ux - uy * uy);
}

__global__ void init_x_kernel(const int* __restrict__ Z,
                              const float* __restrict__ embed, int N) {
    int i = blockIdx.x * blockDim.x + threadIdx.x;
    if (i >= N * FT) return;
    int n = i >> 5, f = i & 31;
    g_x[(n * 9) * FT + f] = embed[Z[n] * FT + f];
}

__global__ void zero_y_kernel(int count) {
    int i = blockIdx.x * blockDim.x + threadIdx.x;
    if (i < count) g_y[i] = 0.0f;
}

template <int IT>
__global__ void edge_kernel(const float* __restrict__ W,
                            const int* __restrict__ nbr, int E) {
    using P = PathsT<IT>;
    constexpr int NP = P::NP;
    constexpr int DO = (IT == 2) ? 1 : 9;
    constexpr int DX = (IT == 0) ? 1 : 9;

    int lane = threadIdx.x & 31;
    int e = (blockIdx.x * blockDim.x + threadIdx.x) >> 5;
    if (e >= E) return;

    int d = nbr[e];       // idx_i = dst
    int s = nbr[E + e];   // idx_j = src

    float Yv[9];
#pragma unroll
    for (int b = 0; b < 9; ++b) Yv[b] = g_Y[e * 9 + b];
    float rad[8];
#pragma unroll
    for (int n = 0; n < 8; ++n) rad[n] = g_rad[e * 8 + n];

    float xs[DX];
#pragma unroll
    for (int a = 0; a < DX; ++a) xs[a] = g_x[(s * 9 + a) * FT + lane];

    float out[DO];
#pragma unroll
    for (int c = 0; c < DO; ++c) out[c] = 0.0f;

    sfor<NP>([&](auto PI) {
        constexpr int p = decltype(PI)::v;
        constexpr int l1 = P::L[p][0], l2 = P::L[p][1], l3 = P::L[p][2];
        constexpr int o1 = cgct::o_of(l1), o2 = cgct::o_of(l2), o3 = cgct::o_of(l3);
        float w = 0.0f;
#pragma unroll
        for (int n = 0; n < 8; ++n) w += rad[n] * W[(p * 8 + n) * FT + lane];
        sfor<2 * l1 + 1>([&](auto AI) {
            constexpr int a = decltype(AI)::v;
            float xa = xs[o1 + a] * w;
            sfor<2 * l2 + 1>([&](auto BI) {
                constexpr int b = decltype(BI)::v;
                float xy = xa * Yv[o2 + b];
                sfor<2 * l3 + 1>([&](auto CI) {
                    constexpr int c = decltype(CI)::v;
                    constexpr double cgv = cgct::CGC(o1 + a, o2 + b, o3 + c);
                    if constexpr (cgv != 0.0) {
                        constexpr int oc = (IT == 2) ? 0 : (o3 + c);
                        out[oc] += (float)cgv * xy;
                    }
                });
            });
        });
    });

#pragma unroll
    for (int c = 0; c < DO; ++c)
        atomicAdd(&g_y[(d * DO + c) * FT + lane], out[c]);
}

template <int IT>
__global__ void node_kernel(const float* __restrict__ K1, const float* __restrict__ b1,
                            const float* __restrict__ K2, const float* __restrict__ b2,
                            float* __restrict__ outp, int N) {
    int lane = threadIdx.x & 31;
    int n = (blockIdx.x * blockDim.x + threadIdx.x) >> 5;
    if (n >= N) return;
    constexpr int D = (IT == 2) ? 1 : 9;

    float xo[D], t[D];
    if constexpr (IT == 0) {
        xo[0] = g_x[(n * 9) * FT + lane];
        t[0] = g_y[(n * 9) * FT + lane] + xo[0];
#pragma unroll
        for (int c = 1; c < 9; ++c) t[c] = g_y[(n * 9 + c) * FT + lane];
    } else if constexpr (IT == 1) {
#pragma unroll
        for (int c = 0; c < 9; ++c) {
            xo[c] = g_x[(n * 9 + c) * FT + lane];
            t[c] = xo[c] + g_y[(n * 9 + c) * FT + lane];
        }
    } else {
        xo[0] = g_x[(n * 9) * FT + lane];
        t[0] = xo[0] + g_y[n * FT + lane];
    }

    // dense1: u[c][g] = sum_f t[c][f] * K1[f][g] ; bias on channel 0
    float u[D];
#pragma unroll
    for (int c = 0; c < D; ++c) u[c] = (c == 0) ? b1[lane] : 0.0f;
#pragma unroll
    for (int f2 = 0; f2 < 32; ++f2) {
        float kv = K1[f2 * FT + lane];
#pragma unroll
        for (int c = 0; c < D; ++c) {
            float tv = __shfl_sync(0xffffffffu, t[c], f2);
            u[c] += tv * kv;
        }
    }

    // esilu
    float sgt = u[0];
    float sig = 1.0f / (1.0f + expf(-sgt));
    float v[D];
    v[0] = sgt * sig;
#pragma unroll
    for (int c = 1; c < D; ++c) v[c] = u[c] * sig;

    // dense2
    float y2[D];
#pragma unroll
    for (int c = 0; c < D; ++c) y2[c] = (c == 0) ? b2[lane] : 0.0f;
#pragma unroll
    for (int f2 = 0; f2 < 32; ++f2) {
        float kv = K2[f2 * FT + lane];
#pragma unroll
        for (int c = 0; c < D; ++c) {
            float vv = __shfl_sync(0xffffffffu, v[c], f2);
            y2[c] += vv * kv;
        }
    }

    if constexpr (IT == 0) {
        g_x[(n * 9) * FT + lane] = xo[0] + y2[0];
#pragma unroll
        for (int c = 1; c < 9; ++c) g_x[(n * 9 + c) * FT + lane] = y2[c];
    } else if constexpr (IT == 1) {
#pragma unroll
        for (int c = 0; c < 9; ++c) g_x[(n * 9 + c) * FT + lane] = xo[c] + y2[c];
    } else {
        outp[n * FT + lane] = xo[0] + y2[0];
    }
}

// ============================================================================
// launch
// ============================================================================
extern "C" void kernel_launch(void* const* d_in, const int* in_sizes, int n_in,
                              void* d_out, int out_size) {
    const float* dr    = (const float*)d_in[0];
    const int*   Z     = (const int*)d_in[1];
    const int*   nbr   = (const int*)d_in[2];
    const float* embed = (const float*)d_in[3];
    const float* w0    = (const float*)d_in[4];
    const float* w1    = (const float*)d_in[5];
    const float* w2    = (const float*)d_in[6];
    const float* k1    = (const float*)d_in[7];
    const float* b1    = (const float*)d_in[8];
    const float* k2    = (const float*)d_in[9];
    const float* b2    = (const float*)d_in[10];
    float* outp = (float*)d_out;

    int E = in_sizes[0] / 3;
    int N = in_sizes[1];

    geom_kernel<<<(E + 255) / 256, 256>>>(dr, nbr, E);
    init_x_kernel<<<(N * 32 + 255) / 256, 256>>>(Z, embed, N);

    int ew_blocks = (E * 32 + 255) / 256;
    int nw_blocks = (N * 32 + 255) / 256;

    // iteration 0
    zero_y_kernel<<<(N * 9 * 32 + 255) / 256, 256>>>(N * 9 * 32);
    edge_kernel<0><<<ew_blocks, 256>>>(w0, nbr, E);
    node_kernel<0><<<nw_blocks, 256>>>(k1, b1, k2, b2, nullptr, N);

    // iteration 1
    zero_y_kernel<<<(N * 9 * 32 + 255) / 256, 256>>>(N * 9 * 32);
    edge_kernel<1><<<ew_blocks, 256>>>(w1, nbr, E);
    node_kernel<1><<<nw_blocks, 256>>>(k1 + 1024, b1 + 32, k2 + 1024, b2 + 32, nullptr, N);

    // iteration 2
    zero_y_kernel<<<(N * 32 + 255) / 256, 256>>>(N * 32);
    edge_kernel<2><<<ew_blocks, 256>>>(w2, nbr, E);
    node_kernel<2><<<nw_blocks, 256>>>(k1 + 2048, b1 + 64, k2 + 2048, b2 + 64, outp, N);
}

// round 2
// speedup vs baseline: 1.1488x; 1.1488x over previous
#include <cuda_runtime.h>
#include <math.h>

// ============================================================================
// Compile-time real Clebsch-Gordan tensor (exact replica of the reference's
// _real_cg, evaluated at C++ compile time so zero coefficients vanish).
// ============================================================================
#define DH __host__ __device__

namespace cgct {

DH constexpr double fact(int n) {
    double r = 1.0;
    for (int i = 2; i <= n; ++i) r *= (double)i;
    return r;
}

DH constexpr double csqrt(double x) {
    if (x <= 0.0) return 0.0;
    double g = x < 1.0 ? 1.0 : x;
    for (int i = 0; i < 200; ++i) g = 0.5 * (g + x / g);
    return g;
}

DH constexpr int iabs(int x) { return x < 0 ? -x : x; }
DH constexpr double m1p(int k) { return (k % 2 != 0) ? -1.0 : 1.0; }

DH constexpr double clebsch(int j1, int m1, int j2, int m2, int j3, int m3) {
    if (m1 + m2 != m3) return 0.0;
    if (j3 < iabs(j1 - j2) || j3 > j1 + j2) return 0.0;
    double pre = csqrt((2.0 * j3 + 1.0) * fact(j1 + j2 - j3) * fact(j1 - j2 + j3) *
                       fact(-j1 + j2 + j3) / fact(j1 + j2 + j3 + 1));
    pre = pre * csqrt(fact(j3 + m3) * fact(j3 - m3) * fact(j1 - m1) *
                      fact(j1 + m1) * fact(j2 - m2) * fact(j2 + m2));
    double s = 0.0;
    for (int k = 0; k <= j1 + j2 + j3; ++k) {
        int d0 = k, d1 = j1 + j2 - j3 - k, d2 = j1 - m1 - k;
        int d3 = j2 + m2 - k, d4 = j3 - j2 + m1 + k, d5 = j3 - j1 - m2 + k;
        if (d0 < 0 || d1 < 0 || d2 < 0 || d3 < 0 || d4 < 0 || d5 < 0) continue;
        s += m1p(k) / (fact(d0) * fact(d1) * fact(d2) * fact(d3) * fact(d4) * fact(d5));
    }
    return pre * s;
}

struct C2 { double re, im; };
DH constexpr C2 cmul(C2 a, C2 b) { return {a.re * b.re - a.im * b.im, a.re * b.im + a.im * b.re}; }
DH constexpr C2 cconj(C2 a) { return {a.re, -a.im}; }

DH constexpr C2 Uel(int l, int i, int k) {
    double s2 = 1.0 / csqrt(2.0);
    int m = i - l;
    if (m == 0) return (k == l) ? C2{1.0, 0.0} : C2{0.0, 0.0};
    if (m > 0) {
        if (k == l + m) return C2{m1p(m) * s2, 0.0};
        if (k == l - m) return C2{s2, 0.0};
        return C2{0.0, 0.0};
    }
    if (k == l + m) return C2{0.0, s2};
    if (k == l - m) return C2{0.0, -m1p(m) * s2};
    return C2{0.0, 0.0};
}

DH constexpr int l_of(int I) { return I == 0 ? 0 : (I < 4 ? 1 : 2); }
DH constexpr int o_of(int l) { return l == 0 ? 0 : (l == 1 ? 1 : 4); }

DH constexpr double CGC(int I, int J, int K) {
    int l1 = l_of(I), l2 = l_of(J), l3 = l_of(K);
    if (l3 < iabs(l1 - l2) || l3 > l1 + l2) return 0.0;
    int i = I - o_of(l1), j = J - o_of(l2), kk = K - o_of(l3);
    double re = 0.0, im = 0.0;
    for (int a = 0; a < 2 * l1 + 1; ++a) {
        for (int b = 0; b < 2 * l2 + 1; ++b) {
            int m1 = a - l1, m2 = b - l2, m3 = m1 + m2;
            if (m3 < -l3 || m3 > l3) continue;
            int c = m3 + l3;
            double v = clebsch(l1, m1, l2, m2, l3, m3);
            if (v == 0.0) continue;
            C2 t = cmul(cmul(Uel(l1, i, a), Uel(l2, j, b)), cconj(Uel(l3, kk, c)));
            re += t.re * v;
            im += t.im * v;
        }
    }
    return re + im;
}

} // namespace cgct

// ============================================================================
// static-for
// ============================================================================
template <int I> struct IC { static constexpr int v = I; };
template <int N, class F>
__device__ __forceinline__ void sfor(F&& f) {
    if constexpr (N > 0) {
        sfor<N - 1>(f);
        f(IC<N - 1>{});
    }
}

// ============================================================================
// Problem constants & scratch
// ============================================================================
constexpr int NE = 320000;
constexpr int NN = 10000;
constexpr int FT = 32;

// packed per-edge geometry: [0..8]=Y, [8..11]=pad (Y8 in gg[2].x), [12..19]=rad
__device__ float4 g_geom[NE * 5];
__device__ float g_x[NN * 9 * FT];
__device__ float g_y[NN * 9 * FT];

// Path lists
template <int IT> struct PathsT;
template <> struct PathsT<0> {
    static constexpr int NP = 3;
    static constexpr int L[3][3] = {{0,0,0},{0,1,1},{0,2,2}};
};
template <> struct PathsT<1> {
    static constexpr int NP = 15;
    static constexpr int L[15][3] = {
        {0,0,0},{0,1,1},{0,2,2},
        {1,0,1},{1,1,0},{1,1,1},{1,1,2},{1,2,1},{1,2,2},
        {2,0,2},{2,1,1},{2,1,2},{2,2,0},{2,2,1},{2,2,2}};
};
template <> struct PathsT<2> {
    static constexpr int NP = 3;
    static constexpr int L[3][3] = {{0,0,0},{1,1,0},{2,2,0}};
};

// ============================================================================
// Kernels
// ============================================================================
__global__ void geom_kernel(const float* __restrict__ dr,
                            const int* __restrict__ nbr, int E) {
    int e = blockIdx.x * blockDim.x + threadIdx.x;
    if (e >= E) return;
    float dx = dr[e * 3 + 0], dy = dr[e * 3 + 1], dz = dr[e * 3 + 2];
    float r2 = dx * dx + dy * dy + dz * dz + 1e-12f;
    float r = sqrtf(r2);
    float inv = 1.0f / r;
    float ux = dx * inv, uy = dy * inv, uz = dz * inv;

    float t = r * (1.0f / 6.0f);
    t = fminf(fmaxf(t, 0.0f), 1.0f - 1e-6f);
    float cut = (r < 6.0f) ? expf(1.0f - 1.0f / (1.0f - t * t)) : 0.0f;

    int ii = nbr[e], jj = nbr[E + e];
    float cm = cut * ((ii != jj) ? 1.0f : 0.0f);

    const float pre = 0.5773502691896258f;  // sqrt(2/6)
    float arg = 0.5235987755982988f * r;    // pi*r/6
    float s = pre * inv * cm;

    // sin(n*arg) via recurrence: s_{n+1} = 2 cos(arg) s_n - s_{n-1}
    float s1, c1;
    sincosf(arg, &s1, &c1);
    float tc = 2.0f * c1;
    float rad[8];
    float sp = 0.0f, sc = s1;
#pragma unroll
    for (int n = 0; n < 8; ++n) {
        rad[n] = s * sc;
        float nxt = tc * sc - sp;
        sp = sc;
        sc = nxt;
    }

    const float c0 = 0.28209479177387814f, c1y = 0.4886025119029199f;
    const float c2a = 1.0925484305920792f, c2b = 0.31539156525252005f,
                c2c = 0.5462742152960396f;
    float4* gg = &g_geom[e * 5];
    gg[0] = make_float4(c0, c1y * uy, c1y * uz, c1y * ux);
    gg[1] = make_float4(c2a * ux * uy, c2a * uy * uz,
                        c2b * (3.0f * uz * uz - 1.0f), c2a * ux * uz);
    gg[2] = make_float4(c2c * (ux * ux - uy * uy), 0.0f, 0.0f, 0.0f);
    gg[3] = make_float4(rad[0], rad[1], rad[2], rad[3]);
    gg[4] = make_float4(rad[4], rad[5], rad[6], rad[7]);
}

__global__ void init_x_kernel(const int* __restrict__ Z,
                              const float* __restrict__ embed, int N) {
    int i = blockIdx.x * blockDim.x + threadIdx.x;
    if (i >= N * FT) return;
    int n = i >> 5, f = i & 31;
    g_x[(n * 9) * FT + f] = embed[Z[n] * FT + f];
}

__global__ void zero_y_kernel(int count4) {
    int i = blockIdx.x * blockDim.x + threadIdx.x;
    if (i < count4) ((float4*)g_y)[i] = make_float4(0.f, 0.f, 0.f, 0.f);
}

template <int IT>
__global__ void __launch_bounds__(256)
edge_kernel(const float* __restrict__ W, const int* __restrict__ nbr, int E) {
    using P = PathsT<IT>;
    constexpr int NP = P::NP;
    constexpr int DO = (IT == 2) ? 1 : 9;
    constexpr int DX = (IT == 0) ? 1 : 9;

    int lane = threadIdx.x & 31;

    // Hold the full weight tensor for this lane's feature in registers —
    // it is reused for every edge this warp processes.
    float Wr[NP * 8];
#pragma unroll
    for (int i = 0; i < NP * 8; ++i) Wr[i] = W[i * FT + lane];

    int warp = (blockIdx.x * blockDim.x + threadIdx.x) >> 5;
    int nwarps = (gridDim.x * blockDim.x) >> 5;

    for (int e = warp; e < E; e += nwarps) {
        int d = nbr[e];       // idx_i = dst
        int s = nbr[E + e];   // idx_j = src

        const float4* gg = &g_geom[e * 5];
        float4 ya = gg[0], yb = gg[1];
        float Y8 = gg[2].x;
        float4 ra = gg[3], rb = gg[4];
        float Yv[9] = {ya.x, ya.y, ya.z, ya.w, yb.x, yb.y, yb.z, yb.w, Y8};
        float rad[8] = {ra.x, ra.y, ra.z, ra.w, rb.x, rb.y, rb.z, rb.w};

        float xs[DX];
#pragma unroll
        for (int a = 0; a < DX; ++a) xs[a] = g_x[(s * 9 + a) * FT + lane];

        float out[DO];
#pragma unroll
        for (int c = 0; c < DO; ++c) out[c] = 0.0f;

        sfor<NP>([&](auto PI) {
            constexpr int p = decltype(PI)::v;
            constexpr int l1 = P::L[p][0], l2 = P::L[p][1], l3 = P::L[p][2];
            constexpr int o1 = cgct::o_of(l1), o2 = cgct::o_of(l2), o3 = cgct::o_of(l3);
            float w = 0.0f;
#pragma unroll
            for (int n = 0; n < 8; ++n) w += rad[n] * Wr[p * 8 + n];
            sfor<2 * l1 + 1>([&](auto AI) {
                constexpr int a = decltype(AI)::v;
                float xa = xs[o1 + a] * w;
                sfor<2 * l2 + 1>([&](auto BI) {
                    constexpr int b = decltype(BI)::v;
                    float xy = xa * Yv[o2 + b];
                    sfor<2 * l3 + 1>([&](auto CI) {
                        constexpr int c = decltype(CI)::v;
                        constexpr double cgv = cgct::CGC(o1 + a, o2 + b, o3 + c);
                        if constexpr (cgv != 0.0) {
                            constexpr int oc = (IT == 2) ? 0 : (o3 + c);
                            out[oc] += (float)cgv * xy;
                        }
                    });
                });
            });
        });

#pragma unroll
        for (int c = 0; c < DO; ++c)
            atomicAdd(&g_y[(d * DO + c) * FT + lane], out[c]);
    }
}

template <int IT>
__global__ void node_kernel(const float* __restrict__ K1, const float* __restrict__ b1,
                            const float* __restrict__ K2, const float* __restrict__ b2,
                            float* __restrict__ outp, int N) {
    int lane = threadIdx.x & 31;
    int n = (blockIdx.x * blockDim.x + threadIdx.x) >> 5;
    if (n >= N) return;
    constexpr int D = (IT == 2) ? 1 : 9;

    float xo[D], t[D];
    if constexpr (IT == 0) {
        xo[0] = g_x[(n * 9) * FT + lane];
        t[0] = g_y[(n * 9) * FT + lane] + xo[0];
#pragma unroll
        for (int c = 1; c < 9; ++c) t[c] = g_y[(n * 9 + c) * FT + lane];
    } else if constexpr (IT == 1) {
#pragma unroll
        for (int c = 0; c < 9; ++c) {
            xo[c] = g_x[(n * 9 + c) * FT + lane];
            t[c] = xo[c] + g_y[(n * 9 + c) * FT + lane];
        }
    } else {
        xo[0] = g_x[(n * 9) * FT + lane];
        t[0] = xo[0] + g_y[n * FT + lane];
    }

    float u[D];
#pragma unroll
    for (int c = 0; c < D; ++c) u[c] = (c == 0) ? b1[lane] : 0.0f;
#pragma unroll
    for (int f2 = 0; f2 < 32; ++f2) {
        float kv = K1[f2 * FT + lane];
#pragma unroll
        for (int c = 0; c < D; ++c) {
            float tv = __shfl_sync(0xffffffffu, t[c], f2);
            u[c] += tv * kv;
        }
    }

    float sgt = u[0];
    float sig = 1.0f / (1.0f + expf(-sgt));
    float v[D];
    v[0] = sgt * sig;
#pragma unroll
    for (int c = 1; c < D; ++c) v[c] = u[c] * sig;

    float y2[D];
#pragma unroll
    for (int c = 0; c < D; ++c) y2[c] = (c == 0) ? b2[lane] : 0.0f;
#pragma unroll
    for (int f2 = 0; f2 < 32; ++f2) {
        float kv = K2[f2 * FT + lane];
#pragma unroll
        for (int c = 0; c < D; ++c) {
            float vv = __shfl_sync(0xffffffffu, v[c], f2);
            y2[c] += vv * kv;
        }
    }

    if constexpr (IT == 0) {
        g_x[(n * 9) * FT + lane] = xo[0] + y2[0];
#pragma unroll
        for (int c = 1; c < 9; ++c) g_x[(n * 9 + c) * FT + lane] = y2[c];
    } else if constexpr (IT == 1) {
#pragma unroll
        for (int c = 0; c < 9; ++c) g_x[(n * 9 + c) * FT + lane] = xo[c] + y2[c];
    } else {
        outp[n * FT + lane] = xo[0] + y2[0];
    }
}

// ============================================================================
// launch
// ============================================================================
extern "C" void kernel_launch(void* const* d_in, const int* in_sizes, int n_in,
                              void* d_out, int out_size) {
    const float* dr    = (const float*)d_in[0];
    const int*   Z     = (const int*)d_in[1];
    const int*   nbr   = (const int*)d_in[2];
    const float* embed = (const float*)d_in[3];
    const float* w0    = (const float*)d_in[4];
    const float* w1    = (const float*)d_in[5];
    const float* w2    = (const float*)d_in[6];
    const float* k1    = (const float*)d_in[7];
    const float* b1    = (const float*)d_in[8];
    const float* k2    = (const float*)d_in[9];
    const float* b2    = (const float*)d_in[10];
    float* outp = (float*)d_out;

    int E = in_sizes[0] / 3;
    int N = in_sizes[1];

    geom_kernel<<<(E + 255) / 256, 256>>>(dr, nbr, E);
    init_x_kernel<<<(N * 32 + 255) / 256, 256>>>(Z, embed, N);

    const int EB = 592;   // grid-stride blocks for edge kernels (4 per SM nominal)
    int nw_blocks = (N * 32 + 255) / 256;
    int z9 = N * 9 * 32 / 4, z1 = N * 32 / 4;

    // iteration 0
    zero_y_kernel<<<(z9 + 255) / 256, 256>>>(z9);
    edge_kernel<0><<<EB, 256>>>(w0, nbr, E);
    node_kernel<0><<<nw_blocks, 256>>>(k1, b1, k2, b2, nullptr, N);

    // iteration 1
    zero_y_kernel<<<(z9 + 255) / 256, 256>>>(z9);
    edge_kernel<1><<<EB, 256>>>(w1, nbr, E);
    node_kernel<1><<<nw_blocks, 256>>>(k1 + 1024, b1 + 32, k2 + 1024, b2 + 32, nullptr, N);

    // iteration 2
    zero_y_kernel<<<(z1 + 255) / 256, 256>>>(z1);
    edge_kernel<2><<<EB, 256>>>(w2, nbr, E);
    node_kernel<2><<<nw_blocks, 256>>>(k1 + 2048, b1 + 64, k2 + 2048, b2 + 64, outp, N);
}

// round 3
// speedup vs baseline: 1.2991x; 1.1309x over previous
#include <cuda_runtime.h>
#include <math.h>

// ============================================================================
// Compile-time real Clebsch-Gordan tensor (exact replica of reference _real_cg)
// ============================================================================
#define DH __host__ __device__

namespace cgct {

DH constexpr double fact(int n) {
    double r = 1.0;
    for (int i = 2; i <= n; ++i) r *= (double)i;
    return r;
}

DH constexpr double csqrt(double x) {
    if (x <= 0.0) return 0.0;
    double g = x < 1.0 ? 1.0 : x;
    for (int i = 0; i < 200; ++i) g = 0.5 * (g + x / g);
    return g;
}

DH constexpr int iabs(int x) { return x < 0 ? -x : x; }
DH constexpr double m1p(int k) { return (k % 2 != 0) ? -1.0 : 1.0; }

DH constexpr double clebsch(int j1, int m1, int j2, int m2, int j3, int m3) {
    if (m1 + m2 != m3) return 0.0;
    if (j3 < iabs(j1 - j2) || j3 > j1 + j2) return 0.0;
    double pre = csqrt((2.0 * j3 + 1.0) * fact(j1 + j2 - j3) * fact(j1 - j2 + j3) *
                       fact(-j1 + j2 + j3) / fact(j1 + j2 + j3 + 1));
    pre = pre * csqrt(fact(j3 + m3) * fact(j3 - m3) * fact(j1 - m1) *
                      fact(j1 + m1) * fact(j2 - m2) * fact(j2 + m2));
    double s = 0.0;
    for (int k = 0; k <= j1 + j2 + j3; ++k) {
        int d0 = k, d1 = j1 + j2 - j3 - k, d2 = j1 - m1 - k;
        int d3 = j2 + m2 - k, d4 = j3 - j2 + m1 + k, d5 = j3 - j1 - m2 + k;
        if (d0 < 0 || d1 < 0 || d2 < 0 || d3 < 0 || d4 < 0 || d5 < 0) continue;
        s += m1p(k) / (fact(d0) * fact(d1) * fact(d2) * fact(d3) * fact(d4) * fact(d5));
    }
    return pre * s;
}

struct C2 { double re, im; };
DH constexpr C2 cmul(C2 a, C2 b) { return {a.re * b.re - a.im * b.im, a.re * b.im + a.im * b.re}; }
DH constexpr C2 cconj(C2 a) { return {a.re, -a.im}; }

DH constexpr C2 Uel(int l, int i, int k) {
    double s2 = 1.0 / csqrt(2.0);
    int m = i - l;
    if (m == 0) return (k == l) ? C2{1.0, 0.0} : C2{0.0, 0.0};
    if (m > 0) {
        if (k == l + m) return C2{m1p(m) * s2, 0.0};
        if (k == l - m) return C2{s2, 0.0};
        return C2{0.0, 0.0};
    }
    if (k == l + m) return C2{0.0, s2};
    if (k == l - m) return C2{0.0, -m1p(m) * s2};
    return C2{0.0, 0.0};
}

DH constexpr int l_of(int I) { return I == 0 ? 0 : (I < 4 ? 1 : 2); }
DH constexpr int o_of(int l) { return l == 0 ? 0 : (l == 1 ? 1 : 4); }

DH constexpr double CGC(int I, int J, int K) {
    int l1 = l_of(I), l2 = l_of(J), l3 = l_of(K);
    if (l3 < iabs(l1 - l2) || l3 > l1 + l2) return 0.0;
    int i = I - o_of(l1), j = J - o_of(l2), kk = K - o_of(l3);
    double re = 0.0, im = 0.0;
    for (int a = 0; a < 2 * l1 + 1; ++a) {
        for (int b = 0; b < 2 * l2 + 1; ++b) {
            int m1 = a - l1, m2 = b - l2, m3 = m1 + m2;
            if (m3 < -l3 || m3 > l3) continue;
            int c = m3 + l3;
            double v = clebsch(l1, m1, l2, m2, l3, m3);
            if (v == 0.0) continue;
            C2 t = cmul(cmul(Uel(l1, i, a), Uel(l2, j, b)), cconj(Uel(l3, kk, c)));
            re += t.re * v;
            im += t.im * v;
        }
    }
    return re + im;
}

// does (I,J) have any nonzero CG into block l3 at offset o3?
DH constexpr bool anyNZ(int I, int J, int o3, int nl3) {
    for (int c = 0; c < nl3; ++c)
        if (CGC(I, J, o3 + c) != 0.0) return true;
    return false;
}

} // namespace cgct

// ============================================================================
// static-for
// ============================================================================
template <int I> struct IC { static constexpr int v = I; };
template <int N, class F>
__device__ __forceinline__ void sfor(F&& f) {
    if constexpr (N > 0) {
        sfor<N - 1>(f);
        f(IC<N - 1>{});
    }
}

// ============================================================================
// packed f32x2 helpers
// ============================================================================
using u64 = unsigned long long;

__device__ __forceinline__ u64 pk2(float lo, float hi) {
    u64 r;
    asm("mov.b64 %0, {%1, %2};" : "=l"(r) : "f"(lo), "f"(hi));
    return r;
}
__device__ __forceinline__ u64 pk1(float v) { return pk2(v, v); }
__device__ __forceinline__ void upk(u64 v, float& lo, float& hi) {
    asm("mov.b64 {%0, %1}, %2;" : "=f"(lo), "=f"(hi) : "l"(v));
}
__device__ __forceinline__ u64 f2mul(u64 a, u64 b) {
    u64 d;
    asm("mul.rn.f32x2 %0, %1, %2;" : "=l"(d) : "l"(a), "l"(b));
    return d;
}
__device__ __forceinline__ u64 f2fma(u64 a, u64 b, u64 c) {
    u64 d;
    asm("fma.rn.f32x2 %0, %1, %2, %3;" : "=l"(d) : "l"(a), "l"(b), "l"(c));
    return d;
}

// ============================================================================
// Problem constants & scratch
// ============================================================================
constexpr int NE = 320000;
constexpr int NN_MAX = 10240;
constexpr int FT = 32;

__device__ float4 g_geom[NE * 5];   // permuted to sorted order
__device__ int2   g_sd[NE];         // (src, dst), sorted by dst
__device__ int    g_pos[NE];        // original edge -> sorted position
__device__ int    g_cnt[NN_MAX];
__device__ int    g_off[NN_MAX];
__device__ float  g_x[10000 * 9 * FT];
__device__ float  g_y[10000 * 9 * FT];

// Path lists
template <int IT> struct PathsT;
template <> struct PathsT<0> {
    static constexpr int L[3][3] = {{0,0,0},{0,1,1},{0,2,2}};
};
template <> struct PathsT<1> {
    static constexpr int L[15][3] = {
        {0,0,0},{0,1,1},{0,2,2},
        {1,0,1},{1,1,0},{1,1,1},{1,1,2},{1,2,1},{1,2,2},
        {2,0,2},{2,1,1},{2,1,2},{2,2,0},{2,2,1},{2,2,2}};
};
template <> struct PathsT<2> {
    static constexpr int L[3][3] = {{0,0,0},{1,1,0},{2,2,0}};
};

// ============================================================================
// Sort kernels (counting sort by dst)
// ============================================================================
__global__ void zero_cnt_kernel(int N) {
    int i = blockIdx.x * blockDim.x + threadIdx.x;
    if (i < N) g_cnt[i] = 0;
}

__global__ void hist_kernel(const int* __restrict__ nbr, int E) {
    int e = blockIdx.x * blockDim.x + threadIdx.x;
    if (e < E) atomicAdd(&g_cnt[nbr[e]], 1);
}

__global__ void scan_kernel(int N) {
    __shared__ int ps[1024];
    int tid = threadIdx.x;
    const int PER = 10;
    int base = tid * PER;
    int loc[PER];
    int s = 0;
#pragma unroll
    for (int i = 0; i < PER; ++i) {
        int idx = base + i;
        int v = (idx < N) ? g_cnt[idx] : 0;
        loc[i] = s;
        s += v;
    }
    ps[tid] = s;
    __syncthreads();
    for (int off = 1; off < 1024; off <<= 1) {
        int v = (tid >= off) ? ps[tid - off] : 0;
        __syncthreads();
        ps[tid] += v;
        __syncthreads();
    }
    int pre = (tid > 0) ? ps[tid - 1] : 0;
#pragma unroll
    for (int i = 0; i < PER; ++i) {
        int idx = base + i;
        if (idx < N) g_off[idx] = pre + loc[i];
    }
}

__global__ void scatter_kernel(const int* __restrict__ nbr, int E) {
    int e = blockIdx.x * blockDim.x + threadIdx.x;
    if (e >= E) return;
    int d = nbr[e];
    int pos = atomicAdd(&g_off[d], 1);
    g_pos[e] = pos;
    g_sd[pos] = make_int2(nbr[E + e], d);
}

// ============================================================================
// geom (writes permuted to sorted positions)
// ============================================================================
__global__ void geom_kernel(const float* __restrict__ dr,
                            const int* __restrict__ nbr, int E) {
    int e = blockIdx.x * blockDim.x + threadIdx.x;
    if (e >= E) return;
    float dx = dr[e * 3 + 0], dy = dr[e * 3 + 1], dz = dr[e * 3 + 2];
    float r2 = dx * dx + dy * dy + dz * dz + 1e-12f;
    float r = sqrtf(r2);
    float inv = 1.0f / r;
    float ux = dx * inv, uy = dy * inv, uz = dz * inv;

    float t = r * (1.0f / 6.0f);
    t = fminf(fmaxf(t, 0.0f), 1.0f - 1e-6f);
    float cut = (r < 6.0f) ? expf(1.0f - 1.0f / (1.0f - t * t)) : 0.0f;

    int ii = nbr[e], jj = nbr[E + e];
    float cm = cut * ((ii != jj) ? 1.0f : 0.0f);

    const float pre = 0.5773502691896258f;   // sqrt(2/6)
    float arg = 0.5235987755982988f * r;     // pi*r/6
    float s = pre * inv * cm;

    float s1, c1;
    sincosf(arg, &s1, &c1);
    float tc = 2.0f * c1;
    float rad[8];
    float sp = 0.0f, sc = s1;
#pragma unroll
    for (int n = 0; n < 8; ++n) {
        rad[n] = s * sc;
        float nxt = tc * sc - sp;
        sp = sc;
        sc = nxt;
    }

    const float c0 = 0.28209479177387814f, c1y = 0.4886025119029199f;
    const float c2a = 1.0925484305920792f, c2b = 0.31539156525252005f,
                c2c = 0.5462742152960396f;
    int pos = g_pos[e];
    float4* gg = &g_geom[pos * 5];
    gg[0] = make_float4(c0, c1y * uy, c1y * uz, c1y * ux);
    gg[1] = make_float4(c2a * ux * uy, c2a * uy * uz,
                        c2b * (3.0f * uz * uz - 1.0f), c2a * ux * uz);
    gg[2] = make_float4(c2c * (ux * ux - uy * uy), 0.0f, 0.0f, 0.0f);
    gg[3] = make_float4(rad[0], rad[1], rad[2], rad[3]);
    gg[4] = make_float4(rad[4], rad[5], rad[6], rad[7]);
}

__global__ void init_x_kernel(const int* __restrict__ Z,
                              const float* __restrict__ embed, int N) {
    int i = blockIdx.x * blockDim.x + threadIdx.x;
    if (i >= N * FT) return;
    int n = i >> 5, f = i & 31;
    g_x[(n * 9) * FT + f] = embed[Z[n] * FT + f];
}

__global__ void zero_y_kernel(int count4) {
    int i = blockIdx.x * blockDim.x + threadIdx.x;
    if (i < count4) ((float4*)g_y)[i] = make_float4(0.f, 0.f, 0.f, 0.f);
}

// ============================================================================
// Packed tensor-product edge kernel.
// Each warp-half (16 lanes) owns a contiguous range of dst-sorted edges.
// lane hl in [0,16) holds features (2hl, 2hl+1) as packed f32x2.
// Accumulates out[] across edges with the same dst, flushes on dst change.
// ============================================================================
template <int IT, int P0, int P1, int XA, int XB, int MINB>
__global__ void __launch_bounds__(256, MINB)
tp_kernel(const float* __restrict__ W, int E, int edges_per_half) {
    using PT = PathsT<IT>;
    constexpr int NPL = P1 - P0;
    constexpr int DO = (IT == 2) ? 1 : 9;
    constexpr int NX = XB - XA;

    int lane = threadIdx.x & 31;
    int hl = lane & 15;

    // weights for this lane's feature pair, in registers
    u64 Wr[NPL * 8];
#pragma unroll
    for (int i = 0; i < NPL * 8; ++i)
        Wr[i] = *(const u64*)(W + (P0 * 8 + i) * FT + 2 * hl);

    int warp = (blockIdx.x * blockDim.x + threadIdx.x) >> 5;
    int halfid = warp * 2 + (lane >> 4);
    int start = halfid * edges_per_half;
    int end = start + edges_per_half;
    if (end > E) end = E;

    u64 out[DO];
#pragma unroll
    for (int c = 0; c < DO; ++c) out[c] = 0;
    int dprev = -1;

    auto flush = [&](int d) {
#pragma unroll
        for (int c = 0; c < DO; ++c) {
            float lo, hi;
            upk(out[c], lo, hi);
            atomicAdd(&g_y[(d * DO + c) * FT + 2 * hl], lo);
            atomicAdd(&g_y[(d * DO + c) * FT + 2 * hl + 1], hi);
            out[c] = 0;
        }
    };

    for (int e = start; e < end; ++e) {
        int2 sd = g_sd[e];
        if (sd.y != dprev) {
            if (dprev >= 0) flush(dprev);
            dprev = sd.y;
        }

        const float4* gg = &g_geom[e * 5];
        float4 A = gg[0], B = gg[1], C4 = gg[2], R0 = gg[3], R1 = gg[4];
        u64 Yp[9] = {pk1(A.x), pk1(A.y), pk1(A.z), pk1(A.w),
                     pk1(B.x), pk1(B.y), pk1(B.z), pk1(B.w), pk1(C4.x)};
        u64 radp[8] = {pk1(R0.x), pk1(R0.y), pk1(R0.z), pk1(R0.w),
                       pk1(R1.x), pk1(R1.y), pk1(R1.z), pk1(R1.w)};

        u64 xs[NX];
#pragma unroll
        for (int a = 0; a < NX; ++a)
            xs[a] = *(const u64*)(g_x + ((sd.x * 9 + XA + a) * FT) + 2 * hl);

        sfor<NPL>([&](auto PI) {
            constexpr int p = P0 + decltype(PI)::v;
            constexpr int l1 = PT::L[p][0], l2 = PT::L[p][1], l3 = PT::L[p][2];
            constexpr int o1 = cgct::o_of(l1), o2 = cgct::o_of(l2), o3 = cgct::o_of(l3);
            u64 w = f2mul(radp[0], Wr[(p - P0) * 8]);
#pragma unroll
            for (int n = 1; n < 8; ++n) w = f2fma(radp[n], Wr[(p - P0) * 8 + n], w);
            sfor<2 * l1 + 1>([&](auto AI) {
                constexpr int a = decltype(AI)::v;
                u64 xa = f2mul(xs[o1 + a - XA], w);
                sfor<2 * l2 + 1>([&](auto BI) {
                    constexpr int b = decltype(BI)::v;
                    if constexpr (cgct::anyNZ(o1 + a, o2 + b, o3, 2 * l3 + 1)) {
                        u64 xy = f2mul(xa, Yp[o2 + b]);
                        sfor<2 * l3 + 1>([&](auto CI) {
                            constexpr int c = decltype(CI)::v;
                            constexpr double cgv = cgct::CGC(o1 + a, o2 + b, o3 + c);
                            if constexpr (cgv != 0.0) {
                                constexpr int oc = (IT == 2) ? 0 : (o3 + c);
                                out[oc] = f2fma(pk1((float)cgv), xy, out[oc]);
                            }
                        });
                    }
                });
            });
        });
    }
    if (dprev >= 0) flush(dprev);
}

// ============================================================================
// node MLP kernels (unchanged)
// ============================================================================
template <int IT>
__global__ void node_kernel(const float* __restrict__ K1, const float* __restrict__ b1,
                            const float* __restrict__ K2, const float* __restrict__ b2,
                            float* __restrict__ outp, int N) {
    int lane = threadIdx.x & 31;
    int n = (blockIdx.x * blockDim.x + threadIdx.x) >> 5;
    if (n >= N) return;
    constexpr int D = (IT == 2) ? 1 : 9;

    float xo[D], t[D];
    if constexpr (IT == 0) {
        xo[0] = g_x[(n * 9) * FT + lane];
        t[0] = g_y[(n * 9) * FT + lane] + xo[0];
#pragma unroll
        for (int c = 1; c < 9; ++c) t[c] = g_y[(n * 9 + c) * FT + lane];
    } else if constexpr (IT == 1) {
#pragma unroll
        for (int c = 0; c < 9; ++c) {
            xo[c] = g_x[(n * 9 + c) * FT + lane];
            t[c] = xo[c] + g_y[(n * 9 + c) * FT + lane];
        }
    } else {
        xo[0] = g_x[(n * 9) * FT + lane];
        t[0] = xo[0] + g_y[n * FT + lane];
    }

    float u[D];
#pragma unroll
    for (int c = 0; c < D; ++c) u[c] = (c == 0) ? b1[lane] : 0.0f;
#pragma unroll
    for (int f2 = 0; f2 < 32; ++f2) {
        float kv = K1[f2 * FT + lane];
#pragma unroll
        for (int c = 0; c < D; ++c) {
            float tv = __shfl_sync(0xffffffffu, t[c], f2);
            u[c] += tv * kv;
        }
    }

    float sgt = u[0];
    float sig = 1.0f / (1.0f + expf(-sgt));
    float v[D];
    v[0] = sgt * sig;
#pragma unroll
    for (int c = 1; c < D; ++c) v[c] = u[c] * sig;

    float y2[D];
#pragma unroll
    for (int c = 0; c < D; ++c) y2[c] = (c == 0) ? b2[lane] : 0.0f;
#pragma unroll
    for (int f2 = 0; f2 < 32; ++f2) {
        float kv = K2[f2 * FT + lane];
#pragma unroll
        for (int c = 0; c < D; ++c) {
            float vv = __shfl_sync(0xffffffffu, v[c], f2);
            y2[c] += vv * kv;
        }
    }

    if constexpr (IT == 0) {
        g_x[(n * 9) * FT + lane] = xo[0] + y2[0];
#pragma unroll
        for (int c = 1; c < 9; ++c) g_x[(n * 9 + c) * FT + lane] = y2[c];
    } else if constexpr (IT == 1) {
#pragma unroll
        for (int c = 0; c < 9; ++c) g_x[(n * 9 + c) * FT + lane] = xo[c] + y2[c];
    } else {
        outp[n * FT + lane] = xo[0] + y2[0];
    }
}

// ============================================================================
// launch
// ============================================================================
static inline int eph(int blocks, int E) {
    int halves = blocks * 16;  // 8 warps/block * 2 halves
    return (E + halves - 1) / halves;
}

extern "C" void kernel_launch(void* const* d_in, const int* in_sizes, int n_in,
                              void* d_out, int out_size) {
    const float* dr    = (const float*)d_in[0];
    const int*   Z     = (const int*)d_in[1];
    const int*   nbr   = (const int*)d_in[2];
    const float* embed = (const float*)d_in[3];
    const float* w0    = (const float*)d_in[4];
    const float* w1    = (const float*)d_in[5];
    const float* w2    = (const float*)d_in[6];
    const float* k1    = (const float*)d_in[7];
    const float* b1    = (const float*)d_in[8];
    const float* k2    = (const float*)d_in[9];
    const float* b2    = (const float*)d_in[10];
    float* outp = (float*)d_out;

    int E = in_sizes[0] / 3;
    int N = in_sizes[1];

    // counting sort by dst
    zero_cnt_kernel<<<(NN_MAX + 255) / 256, 256>>>(NN_MAX);
    hist_kernel<<<(E + 255) / 256, 256>>>(nbr, E);
    scan_kernel<<<1, 1024>>>(N);
    scatter_kernel<<<(E + 255) / 256, 256>>>(nbr, E);

    geom_kernel<<<(E + 255) / 256, 256>>>(dr, nbr, E);
    init_x_kernel<<<(N * 32 + 255) / 256, 256>>>(Z, embed, N);

    const int LB = 296;  // light kernels: 2 blocks/SM
    const int HB = 148;  // heavy kernels: 1 block/SM
    int nw_blocks = (N * 32 + 255) / 256;
    int z9 = N * 9 * 32 / 4, z1 = N * 32 / 4;

    // iteration 0
    zero_y_kernel<<<(z9 + 255) / 256, 256>>>(z9);
    tp_kernel<0, 0, 3, 0, 1, 2><<<LB, 256>>>(w0, E, eph(LB, E));
    node_kernel<0><<<nw_blocks, 256>>>(k1, b1, k2, b2, nullptr, N);

    // iteration 1 (split by l1 group)
    zero_y_kernel<<<(z9 + 255) / 256, 256>>>(z9);
    tp_kernel<1, 0, 3, 0, 1, 2><<<LB, 256>>>(w1, E, eph(LB, E));
    tp_kernel<1, 3, 9, 1, 4, 1><<<HB, 256>>>(w1, E, eph(HB, E));
    tp_kernel<1, 9, 15, 4, 9, 1><<<HB, 256>>>(w1, E, eph(HB, E));
    node_kernel<1><<<nw_blocks, 256>>>(k1 + 1024, b1 + 32, k2 + 1024, b2 + 32, nullptr, N);

    // iteration 2
    zero_y_kernel<<<(z1 + 255) / 256, 256>>>(z1);
    tp_kernel<2, 0, 3, 0, 9, 2><<<LB, 256>>>(w2, E, eph(LB, E));
    node_kernel<2><<<nw_blocks, 256>>>(k1 + 2048, b1 + 64, k2 + 2048, b2 + 64, outp, N);
}